// round 3
// baseline (speedup 1.0000x reference)
#include <cuda_runtime.h>
#include <cstdint>

#define NGT 100
#define TPB 256
#define APT 4
#define ANCHORS_PER_BLOCK (APT * TPB)
#define BMAX 64
#define AMAX 8732

// Scratch (allocation-free: __device__ globals)
__device__ unsigned long long g_gtbest[BMAX * NGT];
__device__ float g_bestv[BMAX * AMAX];
__device__ int   g_besti[BMAX * AMAX];

__global__ void init_kernel(int total) {
    int i = blockIdx.x * blockDim.x + threadIdx.x;
    if (i < total) g_gtbest[i] = 0ull;
}

// Kernel 1: IoU + per-anchor argmax over gts + per-gt argmax over anchors.
// All IoU arithmetic uses __f*_rn intrinsics: bit-exact vs XLA (round-to-nearest
// per op, NO fma contraction). This is load-bearing: tiny gt boxes contained in
// multiple same-shape anchors produce IoU near-ties at the last ulp, and the
// per-gt argmax must resolve them identically to the reference.
__global__ __launch_bounds__(TPB) void iou_kernel(
    const float* __restrict__ gt_boxes,     // [B, NGT, 4] xyxy
    const float* __restrict__ anchors_xyxy, // [A, 4]
    int A)
{
    const int b = blockIdx.y;
    __shared__ float4 sgt[NGT];
    __shared__ float  sga[NGT];
    const int tid = threadIdx.x;

    if (tid < NGT) {
        float4 g = reinterpret_cast<const float4*>(gt_boxes)[b * NGT + tid];
        sgt[tid] = g;
        sga[tid] = __fmul_rn(__fsub_rn(g.z, g.x), __fsub_rn(g.w, g.y));
    }
    __syncthreads();

    const int a0 = blockIdx.x * ANCHORS_PER_BLOCK + tid;

    float4 anc[APT];
    float  aarea[APT];
    bool   valid[APT];
#pragma unroll
    for (int k = 0; k < APT; k++) {
        int a = a0 + k * TPB;
        valid[k] = (a < A);
        int al = valid[k] ? a : (A - 1);
        anc[k] = reinterpret_cast<const float4*>(anchors_xyxy)[al];
        aarea[k] = __fmul_rn(__fsub_rn(anc[k].z, anc[k].x),
                             __fsub_rn(anc[k].w, anc[k].y));
    }

    float bestv[APT];
    int   besti[APT];
#pragma unroll
    for (int k = 0; k < APT; k++) { bestv[k] = -1.0f; besti[k] = 0; }

    for (int n = 0; n < NGT; n++) {
        const float4 g = sgt[n];
        const float  ga = sga[n];
        float rowbest = -1.0f;
        int   rowa = 0;
#pragma unroll
        for (int k = 0; k < APT; k++) {
            float ltx = fmaxf(anc[k].x, g.x);
            float lty = fmaxf(anc[k].y, g.y);
            float rbx = fminf(anc[k].z, g.z);
            float rby = fminf(anc[k].w, g.w);
            float w = fmaxf(__fsub_rn(rbx, ltx), 0.0f);
            float h = fmaxf(__fsub_rn(rby, lty), 0.0f);
            float inter = __fmul_rn(w, h);
            float uni = __fsub_rn(__fadd_rn(aarea[k], ga), inter);
            float iou = __fdiv_rn(inter, uni);
            if (!valid[k]) iou = -1.0f;
            // per-anchor argmax over n, strict > == first-index tie-break
            if (iou > bestv[k]) { bestv[k] = iou; besti[k] = n; }
            // per-gt argmax over this thread's anchors (k ascending => anchor
            // ascending; strict > keeps smallest anchor index on exact ties)
            if (iou > rowbest) { rowbest = iou; rowa = a0 + k * TPB; }
        }
        // Pack (iou, anchor): higher iou wins; on equal iou bits, larger ~a
        // => smaller anchor index wins (matches jnp.argmax first-occurrence).
        unsigned long long packed = 0ull;
        if (rowbest >= 0.0f)
            packed = ((unsigned long long)__float_as_uint(rowbest) << 32)
                   | (unsigned int)(~(unsigned int)rowa);
#pragma unroll
        for (int off = 16; off > 0; off >>= 1) {
            unsigned long long o = __shfl_down_sync(0xFFFFFFFFu, packed, off);
            packed = (packed > o) ? packed : o;
        }
        if ((tid & 31) == 0 && packed != 0ull)
            atomicMax(&g_gtbest[b * NGT + n], packed);
    }

#pragma unroll
    for (int k = 0; k < APT; k++) {
        int a = a0 + k * TPB;
        if (a < A) {
            g_bestv[b * A + a] = bestv[k];
            g_besti[b * A + a] = besti[k];
        }
    }
}

// Kernel 2: scatter override. For each gt n, set its best anchor's match to
// (n, 2.0). On duplicate anchors, last n wins (in-order scatter semantics).
__global__ void override_kernel(int A) {
    const int b = blockIdx.x;
    __shared__ int sa[NGT];
    const int t = threadIdx.x;
    if (t < NGT) {
        unsigned long long p = g_gtbest[b * NGT + t];
        sa[t] = (int)(~(unsigned int)p);  // low 32 bits = ~anchor_idx
    }
    __syncthreads();
    if (t < NGT) {
        int a = sa[t];
        bool last = true;
        for (int m = t + 1; m < NGT; m++)
            if (sa[m] == a) last = false;
        if (last) {
            g_besti[b * A + a] = t;
            g_bestv[b * A + a] = 2.0f;
        }
    }
}

// Kernel 3: gather + encode. Output layout (float32, concatenated tuple order):
// [0, B*A)        encoded_labels
// [B*A, 5*B*A)    encoded (B, A, 4)
// [5*B*A, 6*B*A)  pos_mask (1.0/0.0)
__global__ __launch_bounds__(256) void encode_kernel(
    const int*   __restrict__ gt_labels,      // [B, NGT]
    const float* __restrict__ gt_boxes,       // [B, NGT, 4] xyxy
    const float* __restrict__ anchors_cxcywh, // [A, 4]
    float* __restrict__ out,
    int A, int B)
{
    const int i = blockIdx.x * blockDim.x + threadIdx.x;
    const int total = B * A;
    if (i >= total) return;
    const int b = i / A;
    const int a = i - b * A;

    const float v = g_bestv[i];
    const int   n = g_besti[i];
    const bool pos = (v > 0.5f);

    float4 g = reinterpret_cast<const float4*>(gt_boxes)[b * NGT + n];
    float4 anc = reinterpret_cast<const float4*>(anchors_cxcywh)[a];

    float gcx = __fmul_rn(__fadd_rn(g.x, g.z), 0.5f);   // == /2 exactly
    float gcy = __fmul_rn(__fadd_rn(g.y, g.w), 0.5f);
    float gw = __fsub_rn(g.z, g.x);
    float gh = __fsub_rn(g.w, g.y);

    float ex = __fdiv_rn(__fsub_rn(gcx, anc.x), anc.z);
    float ey = __fdiv_rn(__fsub_rn(gcy, anc.y), anc.w);
    float ew = logf(__fdiv_rn(__fadd_rn(gw, 1e-6f), __fadd_rn(anc.z, 1e-6f)));
    float eh = logf(__fdiv_rn(__fadd_rn(gh, 1e-6f), __fadd_rn(anc.w, 1e-6f)));

    out[i] = pos ? (float)gt_labels[b * NGT + n] : 0.0f;
    reinterpret_cast<float4*>(out + total)[i] = make_float4(ex, ey, ew, eh);
    out[5 * total + i] = pos ? 1.0f : 0.0f;
}

extern "C" void kernel_launch(void* const* d_in, const int* in_sizes, int n_in,
                              void* d_out, int out_size)
{
    const int*   gt_labels      = (const int*)d_in[0];
    const float* gt_boxes       = (const float*)d_in[1];
    const float* anchors_cxcywh = (const float*)d_in[2];
    const float* anchors_xyxy   = (const float*)d_in[3];

    const int A = in_sizes[2] / 4;
    const int B = in_sizes[0] / NGT;

    const int chunks = (A + ANCHORS_PER_BLOCK - 1) / ANCHORS_PER_BLOCK;

    init_kernel<<<(B * NGT + 255) / 256, 256>>>(B * NGT);
    iou_kernel<<<dim3(chunks, B), TPB>>>(gt_boxes, anchors_xyxy, A);
    override_kernel<<<B, 128>>>(A);
    encode_kernel<<<(B * A + 255) / 256, 256>>>(gt_labels, gt_boxes,
                                                anchors_cxcywh,
                                                (float*)d_out, A, B);
}

// round 4
// speedup vs baseline: 1.1021x; 1.1021x over previous
#include <cuda_runtime.h>
#include <cstdint>

#define NGT 100
#define TPB 256
#define APT 4
#define ANCHORS_PER_BLOCK (APT * TPB)
#define BMAX 64
#define AMAX 8732

// Scratch (allocation-free: __device__ globals)
__device__ unsigned long long g_gtbest[BMAX * NGT];
__device__ float g_bestv[BMAX * AMAX];
__device__ int   g_besti[BMAX * AMAX];

__global__ void init_kernel(int total) {
    int i = blockIdx.x * blockDim.x + threadIdx.x;
    if (i < total) g_gtbest[i] = 0ull;
}

// Kernel 1: IoU + per-anchor argmax over gts + per-gt argmax over anchors.
// All IoU arithmetic uses __f*_rn intrinsics: bit-exact vs XLA (round-to-nearest
// per op, NO fma contraction) — load-bearing for ulp-level argmax ties.
// Per-gt warp reduction uses two REDUX.SYNC ops instead of a shfl64 chain.
__global__ __launch_bounds__(TPB) void iou_kernel(
    const float* __restrict__ gt_boxes,     // [B, NGT, 4] xyxy
    const float* __restrict__ anchors_xyxy, // [A, 4]
    int A)
{
    const int b = blockIdx.y;
    __shared__ float4 sgt[NGT];
    __shared__ float  sga[NGT];
    const int tid = threadIdx.x;

    if (tid < NGT) {
        float4 g = reinterpret_cast<const float4*>(gt_boxes)[b * NGT + tid];
        sgt[tid] = g;
        sga[tid] = __fmul_rn(__fsub_rn(g.z, g.x), __fsub_rn(g.w, g.y));
    }
    __syncthreads();

    const int a0 = blockIdx.x * ANCHORS_PER_BLOCK + tid;

    float4 anc[APT];
    float  aarea[APT];
    bool   valid[APT];
#pragma unroll
    for (int k = 0; k < APT; k++) {
        int a = a0 + k * TPB;
        valid[k] = (a < A);
        int al = valid[k] ? a : (A - 1);
        anc[k] = reinterpret_cast<const float4*>(anchors_xyxy)[al];
        aarea[k] = __fmul_rn(__fsub_rn(anc[k].z, anc[k].x),
                             __fsub_rn(anc[k].w, anc[k].y));
    }

    float bestv[APT];
    int   besti[APT];
#pragma unroll
    for (int k = 0; k < APT; k++) { bestv[k] = -1.0f; besti[k] = 0; }

    unsigned long long* gt_row = &g_gtbest[b * NGT];

#pragma unroll 2
    for (int n = 0; n < NGT; n++) {
        const float4 g = sgt[n];
        const float  ga = sga[n];
        float rowbest = -1.0f;
        int   rowa = 0;
#pragma unroll
        for (int k = 0; k < APT; k++) {
            float ltx = fmaxf(anc[k].x, g.x);
            float lty = fmaxf(anc[k].y, g.y);
            float rbx = fminf(anc[k].z, g.z);
            float rby = fminf(anc[k].w, g.w);
            float w = fmaxf(__fsub_rn(rbx, ltx), 0.0f);
            float h = fmaxf(__fsub_rn(rby, lty), 0.0f);
            float inter = __fmul_rn(w, h);
            float uni = __fsub_rn(__fadd_rn(aarea[k], ga), inter);
            float iou = __fdiv_rn(inter, uni);
            if (!valid[k]) iou = -1.0f;
            // per-anchor argmax over n, strict > == first-index tie-break
            if (iou > bestv[k]) { bestv[k] = iou; besti[k] = n; }
            // per-gt argmax over this thread's anchors (k ascending => anchor
            // ascending; strict > keeps smallest anchor index on exact ties)
            if (iou > rowbest) { rowbest = iou; rowa = a0 + k * TPB; }
        }
        // Warp argmax via 2x REDUX: (1) max iou bits (iou>=0 => u32-monotone),
        // (2) among tied lanes, max ~anchor == min anchor index (matches
        // jnp.argmax first-occurrence). Invalid lanes contribute 0.
        unsigned bits = (rowbest >= 0.0f) ? __float_as_uint(rowbest) : 0u;
        unsigned tild = (rowbest >= 0.0f) ? ~(unsigned)rowa : 0u;
        unsigned maxbits = __reduce_max_sync(0xFFFFFFFFu, bits);
        unsigned cand = (bits == maxbits) ? tild : 0u;
        unsigned maxtild = __reduce_max_sync(0xFFFFFFFFu, cand);
        if ((tid & 31) == 0) {
            unsigned long long packed =
                ((unsigned long long)maxbits << 32) | maxtild;
            if (packed) atomicMax(&gt_row[n], packed);
        }
    }

#pragma unroll
    for (int k = 0; k < APT; k++) {
        int a = a0 + k * TPB;
        if (a < A) {
            g_bestv[b * A + a] = bestv[k];
            g_besti[b * A + a] = besti[k];
        }
    }
}

// Kernel 2: scatter override. For each gt n, set its best anchor's match to
// (n, 2.0). On duplicate anchors, last n wins (in-order scatter semantics).
__global__ void override_kernel(int A) {
    const int b = blockIdx.x;
    __shared__ int sa[NGT];
    const int t = threadIdx.x;
    if (t < NGT) {
        unsigned long long p = g_gtbest[b * NGT + t];
        sa[t] = (int)(~(unsigned int)p);  // low 32 bits = ~anchor_idx
    }
    __syncthreads();
    if (t < NGT) {
        int a = sa[t];
        bool last = true;
        for (int m = t + 1; m < NGT; m++)
            if (sa[m] == a) last = false;
        if (last) {
            g_besti[b * A + a] = t;
            g_bestv[b * A + a] = 2.0f;
        }
    }
}

// Kernel 3: gather + encode. Output layout (float32, concatenated tuple order):
// [0, B*A)        encoded_labels
// [B*A, 5*B*A)    encoded (B, A, 4)
// [5*B*A, 6*B*A)  pos_mask (1.0/0.0)
// grid = (ceil(A/256), B) to avoid integer division.
__global__ __launch_bounds__(256) void encode_kernel(
    const int*   __restrict__ gt_labels,      // [B, NGT]
    const float* __restrict__ gt_boxes,       // [B, NGT, 4] xyxy
    const float* __restrict__ anchors_cxcywh, // [A, 4]
    float* __restrict__ out,
    int A, int B)
{
    const int a = blockIdx.x * blockDim.x + threadIdx.x;
    if (a >= A) return;
    const int b = blockIdx.y;
    const int i = b * A + a;
    const int total = B * A;

    const float v = g_bestv[i];
    const int   n = g_besti[i];
    const bool pos = (v > 0.5f);

    float4 g = reinterpret_cast<const float4*>(gt_boxes)[b * NGT + n];
    float4 anc = reinterpret_cast<const float4*>(anchors_cxcywh)[a];

    float gcx = __fmul_rn(__fadd_rn(g.x, g.z), 0.5f);   // == /2 exactly
    float gcy = __fmul_rn(__fadd_rn(g.y, g.w), 0.5f);
    float gw = __fsub_rn(g.z, g.x);
    float gh = __fsub_rn(g.w, g.y);

    float ex = __fdiv_rn(__fsub_rn(gcx, anc.x), anc.z);
    float ey = __fdiv_rn(__fsub_rn(gcy, anc.y), anc.w);
    float ew = logf(__fdiv_rn(__fadd_rn(gw, 1e-6f), __fadd_rn(anc.z, 1e-6f)));
    float eh = logf(__fdiv_rn(__fadd_rn(gh, 1e-6f), __fadd_rn(anc.w, 1e-6f)));

    out[i] = pos ? (float)gt_labels[b * NGT + n] : 0.0f;
    reinterpret_cast<float4*>(out + total)[i] = make_float4(ex, ey, ew, eh);
    out[5 * total + i] = pos ? 1.0f : 0.0f;
}

extern "C" void kernel_launch(void* const* d_in, const int* in_sizes, int n_in,
                              void* d_out, int out_size)
{
    const int*   gt_labels      = (const int*)d_in[0];
    const float* gt_boxes       = (const float*)d_in[1];
    const float* anchors_cxcywh = (const float*)d_in[2];
    const float* anchors_xyxy   = (const float*)d_in[3];

    const int A = in_sizes[2] / 4;
    const int B = in_sizes[0] / NGT;

    const int chunks = (A + ANCHORS_PER_BLOCK - 1) / ANCHORS_PER_BLOCK;

    init_kernel<<<(B * NGT + 255) / 256, 256>>>(B * NGT);
    iou_kernel<<<dim3(chunks, B), TPB>>>(gt_boxes, anchors_xyxy, A);
    override_kernel<<<B, 128>>>(A);
    encode_kernel<<<dim3((A + 255) / 256, B), 256>>>(gt_labels, gt_boxes,
                                                     anchors_cxcywh,
                                                     (float*)d_out, A, B);
}